// round 2
// baseline (speedup 1.0000x reference)
#include <cuda_runtime.h>

#define N_NODES 100000
#define N_EDGES 3200000
#define F_IN 128
#define F_H 32

// ---------------- scratch (static device globals; no allocation) ----------------
__device__ int   g_is64;                    // edge_index dtype flag
__device__ int   g_deg[N_NODES];            // in-degree incl. self loop
__device__ float g_dinv[N_NODES];           // deg^{-1/2}
__device__ int   g_off[N_NODES + 1];        // CSR offsets by destination (real edges only)
__device__ int   g_cursor[N_NODES];
__device__ int   g_rows[N_EDGES];           // CSR source rows
__device__ __align__(16) float g_h1[N_NODES * F_H];   // dinv[r] * (x @ W1)[r]  (pre-scaled)
__device__ __align__(16) float g_a1[N_NODES * F_H];   // tanh(layer-1 output)
__device__ float4 g_h2[N_NODES];            // dinv[r] * (a1 @ W2)[r], padded to 4 floats

// ---------------- kernels ----------------

// Detect int32 vs int64 edge_index: int64 values < 2^31 have odd 32-bit words == 0.
__global__ void k_detect(const int* __restrict__ ei_words) {
    if (threadIdx.x == 0) {
        int all_odd_zero = 1;
        for (int i = 1; i < 16; i += 2)
            if (ei_words[i] != 0) all_odd_zero = 0;
        g_is64 = all_odd_zero;
    }
}

__global__ void k_init() {
    int i = blockIdx.x * blockDim.x + threadIdx.x;
    if (i < N_NODES) { g_deg[i] = 1; g_cursor[i] = 0; }
}

__global__ void k_deg(const void* __restrict__ ei) {
    int e = blockIdx.x * blockDim.x + threadIdx.x;
    if (e >= N_EDGES) return;
    int c;
    if (g_is64) c = (int)((const long long*)ei)[N_EDGES + e];
    else        c = ((const int*)ei)[N_EDGES + e];
    atomicAdd(&g_deg[c], 1);
}

__global__ void k_dinv() {
    int i = blockIdx.x * blockDim.x + threadIdx.x;
    if (i < N_NODES) g_dinv[i] = rsqrtf((float)g_deg[i]);
}

// Single-block exclusive scan of (deg-1) -> CSR offsets
__global__ void k_scan() {
    __shared__ int partial[1024];
    const int T = 1024;
    int t = threadIdx.x;
    const int chunk = (N_NODES + T - 1) / T;
    int start = t * chunk;
    int end = start + chunk; if (end > N_NODES) end = N_NODES;
    int s = 0;
    for (int i = start; i < end; i++) s += g_deg[i] - 1;
    partial[t] = s;
    __syncthreads();
    for (int d = 1; d < T; d <<= 1) {
        int v = (t >= d) ? partial[t - d] : 0;
        __syncthreads();
        partial[t] += v;
        __syncthreads();
    }
    int run = (t == 0) ? 0 : partial[t - 1];
    for (int i = start; i < end; i++) {
        g_off[i] = run;
        run += g_deg[i] - 1;
    }
    if (t == T - 1) g_off[N_NODES] = partial[T - 1];
}

// g_h1[r] = dinv[r] * (x @ W1)[r] : 4 rows per warp, W1 in shared, x via shfl broadcast
__global__ void __launch_bounds__(256) k_h1(const float* __restrict__ x,
                                            const float* __restrict__ W1) {
    __shared__ float sW[F_IN * F_H];   // 16 KB
    for (int i = threadIdx.x; i < F_IN * F_H; i += 256) sW[i] = W1[i];
    __syncthreads();
    int warp = threadIdx.x >> 5, lane = threadIdx.x & 31;
    int row0 = (blockIdx.x * 8 + warp) * 4;
    if (row0 >= N_NODES) return;            // N divisible by 4: whole warp exits together
    const float4* x4 = (const float4*)x;    // 32 float4 per row
    float4 xa = x4[(size_t)(row0 + 0) * 32 + lane];
    float4 xb = x4[(size_t)(row0 + 1) * 32 + lane];
    float4 xc = x4[(size_t)(row0 + 2) * 32 + lane];
    float4 xd = x4[(size_t)(row0 + 3) * 32 + lane];
    float a0 = 0.f, a1 = 0.f, a2 = 0.f, a3 = 0.f;
#pragma unroll
    for (int q = 0; q < 32; q++) {
        float w0 = sW[(4 * q + 0) * F_H + lane];
        float w1 = sW[(4 * q + 1) * F_H + lane];
        float w2 = sW[(4 * q + 2) * F_H + lane];
        float w3 = sW[(4 * q + 3) * F_H + lane];
        a0 += __shfl_sync(0xffffffffu, xa.x, q) * w0;
        a0 += __shfl_sync(0xffffffffu, xa.y, q) * w1;
        a0 += __shfl_sync(0xffffffffu, xa.z, q) * w2;
        a0 += __shfl_sync(0xffffffffu, xa.w, q) * w3;
        a1 += __shfl_sync(0xffffffffu, xb.x, q) * w0;
        a1 += __shfl_sync(0xffffffffu, xb.y, q) * w1;
        a1 += __shfl_sync(0xffffffffu, xb.z, q) * w2;
        a1 += __shfl_sync(0xffffffffu, xb.w, q) * w3;
        a2 += __shfl_sync(0xffffffffu, xc.x, q) * w0;
        a2 += __shfl_sync(0xffffffffu, xc.y, q) * w1;
        a2 += __shfl_sync(0xffffffffu, xc.z, q) * w2;
        a2 += __shfl_sync(0xffffffffu, xc.w, q) * w3;
        a3 += __shfl_sync(0xffffffffu, xd.x, q) * w0;
        a3 += __shfl_sync(0xffffffffu, xd.y, q) * w1;
        a3 += __shfl_sync(0xffffffffu, xd.z, q) * w2;
        a3 += __shfl_sync(0xffffffffu, xd.w, q) * w3;
    }
    g_h1[(size_t)(row0 + 0) * F_H + lane] = a0 * g_dinv[row0 + 0];
    g_h1[(size_t)(row0 + 1) * F_H + lane] = a1 * g_dinv[row0 + 1];
    g_h1[(size_t)(row0 + 2) * F_H + lane] = a2 * g_dinv[row0 + 2];
    g_h1[(size_t)(row0 + 3) * F_H + lane] = a3 * g_dinv[row0 + 3];
}

// Build CSR (counting-sort scatter); only source rows are stored
__global__ void k_csr(const void* __restrict__ ei) {
    int e = blockIdx.x * blockDim.x + threadIdx.x;
    if (e >= N_EDGES) return;
    int r, c;
    if (g_is64) {
        r = (int)((const long long*)ei)[e];
        c = (int)((const long long*)ei)[N_EDGES + e];
    } else {
        r = ((const int*)ei)[e];
        c = ((const int*)ei)[N_EDGES + e];
    }
    int pos = g_off[c] + atomicAdd(&g_cursor[c], 1);
    g_rows[pos] = r;
}

// Layer-1 aggregation + tanh: one warp per node, lane = feature
__global__ void __launch_bounds__(256) k_agg1() {
    int node = (blockIdx.x * blockDim.x + threadIdx.x) >> 5;
    int lane = threadIdx.x & 31;
    if (node >= N_NODES) return;
    int beg = g_off[node], end = g_off[node + 1];
    float acc = g_h1[(size_t)node * F_H + lane];   // self loop (already dinv-scaled)
    int e = beg;
    for (; e + 4 <= end; e += 4) {
        int r0 = g_rows[e + 0], r1 = g_rows[e + 1];
        int r2 = g_rows[e + 2], r3 = g_rows[e + 3];
        acc += g_h1[(size_t)r0 * F_H + lane];
        acc += g_h1[(size_t)r1 * F_H + lane];
        acc += g_h1[(size_t)r2 * F_H + lane];
        acc += g_h1[(size_t)r3 * F_H + lane];
    }
    for (; e < end; e++)
        acc += g_h1[(size_t)g_rows[e] * F_H + lane];
    g_a1[(size_t)node * F_H + lane] = tanhf(acc * g_dinv[node]);
}

// g_h2[c] = dinv[c] * (a1 @ W2)[c]  (32 -> 3, padded to float4): one thread per node
__global__ void k_h2(const float* __restrict__ W2) {
    __shared__ float sW[F_H * 3];
    if (threadIdx.x < F_H * 3) sW[threadIdx.x] = W2[threadIdx.x];
    __syncthreads();
    int c = blockIdx.x * blockDim.x + threadIdx.x;
    if (c >= N_NODES) return;
    const float4* a4 = (const float4*)(g_a1 + (size_t)c * F_H);
    float s0 = 0.f, s1 = 0.f, s2 = 0.f;
#pragma unroll
    for (int q = 0; q < 8; q++) {
        float4 v = a4[q];
        int k = 4 * q;
        s0 += v.x * sW[(k + 0) * 3 + 0]; s1 += v.x * sW[(k + 0) * 3 + 1]; s2 += v.x * sW[(k + 0) * 3 + 2];
        s0 += v.y * sW[(k + 1) * 3 + 0]; s1 += v.y * sW[(k + 1) * 3 + 1]; s2 += v.y * sW[(k + 1) * 3 + 2];
        s0 += v.z * sW[(k + 2) * 3 + 0]; s1 += v.z * sW[(k + 2) * 3 + 1]; s2 += v.z * sW[(k + 2) * 3 + 2];
        s0 += v.w * sW[(k + 3) * 3 + 0]; s1 += v.w * sW[(k + 3) * 3 + 1]; s2 += v.w * sW[(k + 3) * 3 + 2];
    }
    float d = g_dinv[c];
    g_h2[c] = make_float4(d * s0, d * s1, d * s2, 0.f);
}

// Layer-2 aggregation: one warp per node, lanes stride over edges, warp reduce
__global__ void __launch_bounds__(256) k_agg2(float* __restrict__ out) {
    int node = (blockIdx.x * blockDim.x + threadIdx.x) >> 5;
    int lane = threadIdx.x & 31;
    if (node >= N_NODES) return;
    int beg = g_off[node], end = g_off[node + 1];
    float s0 = 0.f, s1 = 0.f, s2 = 0.f;
    for (int e = beg + lane; e < end; e += 32) {
        float4 h = g_h2[g_rows[e]];
        s0 += h.x; s1 += h.y; s2 += h.z;
    }
#pragma unroll
    for (int d = 16; d > 0; d >>= 1) {
        s0 += __shfl_down_sync(0xffffffffu, s0, d);
        s1 += __shfl_down_sync(0xffffffffu, s1, d);
        s2 += __shfl_down_sync(0xffffffffu, s2, d);
    }
    if (lane == 0) {
        float dc = g_dinv[node];
        float4 h = g_h2[node];   // self loop (already dinv-scaled)
        out[(size_t)node * 3 + 0] = dc * (s0 + h.x);
        out[(size_t)node * 3 + 1] = dc * (s1 + h.y);
        out[(size_t)node * 3 + 2] = dc * (s2 + h.z);
    }
}

// ---------------- launcher ----------------
extern "C" void kernel_launch(void* const* d_in, const int* in_sizes, int n_in,
                              void* d_out, int out_size) {
    const float* x  = (const float*)d_in[0];
    const void*  ei = d_in[1];                 // [2, E] int32 or int64 (runtime-detected)
    const float* W1 = (const float*)d_in[2];
    const float* W2 = (const float*)d_in[3];
    float* out = (float*)d_out;

    k_detect<<<1, 32>>>((const int*)ei);
    k_init<<<(N_NODES + 255) / 256, 256>>>();
    k_deg<<<(N_EDGES + 255) / 256, 256>>>(ei);
    k_dinv<<<(N_NODES + 255) / 256, 256>>>();
    k_scan<<<1, 1024>>>();
    k_h1<<<(N_NODES / 4 + 7) / 8, 256>>>(x, W1);   // 4 rows/warp, 8 warps/block
    k_csr<<<(N_EDGES + 255) / 256, 256>>>(ei);
    k_agg1<<<(N_NODES + 7) / 8, 256>>>();          // warp per node
    k_h2<<<(N_NODES + 255) / 256, 256>>>(W2);
    k_agg2<<<(N_NODES + 7) / 8, 256>>>(out);       // warp per node
}